// round 16
// baseline (speedup 1.0000x reference)
#include <cuda_runtime.h>
#include <math.h>

#define NB 128
#define NT 288          // 8 compute warps + 1 monitor warp
#define NTC 256         // compute threads

typedef unsigned long long u64;

constexpr int S_LEN = 1024;
constexpr int B_SZ  = 64;
constexpr int F_DIM = 128;
constexpr int H_DIM = 512;
constexpr int V_DIM = 64;
constexpr int T_LEN = 64;
constexpr int HPB   = H_DIM / NB;        // 4 hidden units per block (16 gate rows)

constexpr int MON_GENS = S_LEN + 2 * T_LEN;   // 1152 monitored barriers

constexpr int W_FLOATS = 640 * 16;       // Wsm[k][16 rows]
constexpr int Z_FLOATS = 128 * 64;       // one 32KB z chunk
constexpr int NZB      = 5;              // z buffers
constexpr int SMEM_FLOATS = W_FLOATS + NZB * Z_FLOATS + 16 + 384;
constexpr int SMEM_BYTES  = SMEM_FLOATS * 4;

// ---------------- persistent device state ----------------
__device__ float g_sigT[S_LEN * F_DIM * B_SZ];   // [t][f][b]
__device__ float g_hT[2][H_DIM * B_SZ];          // [k][b], double buffered
__device__ float g_outWT[H_DIM * V_DIM];         // [k][v]
__device__ int   g_tok[B_SZ];
__device__ u64 g_initCount, g_initGen;           // one-shot init barrier (monotonic)
__device__ u64 g_barGen;                         // step generation (monitor-released)
__device__ u64 g_slot[NB * 16];                  // per-block arrive slots, 128B apart

// ---------------- sync primitives ----------------
__device__ __forceinline__ u64 ld_acq(const u64* p) {
    u64 v; asm volatile("ld.acquire.gpu.u64 %0, [%1];" : "=l"(v) : "l"(p) : "memory");
    return v;
}
__device__ __forceinline__ void st_rel(u64* p, u64 v) {
    asm volatile("st.release.gpu.u64 [%0], %1;" :: "l"(p), "l"(v) : "memory");
}
// named barrier for the 8 compute warps only
__device__ __forceinline__ void cbar() {
    asm volatile("bar.sync 1, 256;" ::: "memory");
}
// init barrier (full block participates; one-shot flat atomic)
__device__ __forceinline__ void init_arrive(u64 igen) {
    __syncthreads();
    if (threadIdx.x == 0) {
        __threadfence();
        u64 v = atomicAdd(&g_initCount, 1ULL);
        if (v == igen * (u64)NB - 1ULL) { __threadfence(); st_rel(&g_initGen, igen); }
    }
}
__device__ __forceinline__ void init_wait(u64 igen) {
    if (threadIdx.x == 0) { while (ld_acq(&g_initGen) < igen) { } }
    __syncthreads();
}
// step barrier: arrive = slot store; release by monitor warp
__device__ __forceinline__ void step_arrive(u64 gen, int blk) {
    cbar();                                   // block's writes done (all 256)
    if (threadIdx.x == 0) {
        __threadfence();
        st_rel(&g_slot[blk * 16], gen);
    }
}
__device__ __forceinline__ void step_wait(u64 gen) {
    if (threadIdx.x == 0) { while (ld_acq(&g_barGen) < gen) { } }
    cbar();
}

__device__ __forceinline__ float sigmoidf(float x) { return 1.0f / (1.0f + expf(-x)); }

// ---------------- packed f32x2 helpers ----------------
__device__ __forceinline__ u64 pack2(float x) {
    unsigned int u = __float_as_uint(x);
    u64 r; asm("mov.b64 %0, {%1, %1};" : "=l"(r) : "r"(u));
    return r;
}
__device__ __forceinline__ void fma2(u64& d, u64 a, u64 b) {
    asm("fma.rn.f32x2 %0, %1, %2, %0;" : "+l"(d) : "l"(a), "l"(b));
}

// ---------------- cp.async helpers ----------------
__device__ __forceinline__ void cp16(unsigned int dst, const float* src) {
    asm volatile("cp.async.ca.shared.global [%0], [%1], 16;" :: "r"(dst), "l"(src));
}
#define CP_COMMIT() asm volatile("cp.async.commit_group;" ::: "memory")
#define CP_WAIT(n)  asm volatile("cp.async.wait_group %0;" :: "n"(n) : "memory")

// stage a 128x64 chunk (8192 floats) smem <- gmem, 8 x 16B per compute thread
__device__ __forceinline__ void cp_chunk(float* dst, const float* src, int tid) {
    unsigned int d = (unsigned int)__cvta_generic_to_shared(dst) + tid * 16;
#pragma unroll
    for (int i = 0; i < 8; ++i)
        cp16(d + i * 4096, src + tid * 4 + i * 1024);
}

// ---------------- chunk compute: 16 k-values, 4 rows x 8 batches ----------------
__device__ __forceinline__ void compute_chunk(const float* __restrict__ Wc,
                                              const float* __restrict__ zc,
                                              u64 acc[16]) {
#pragma unroll
    for (int kk = 0; kk < 16; ++kk) {
        const float* z = zc + kk * 64;
        ulonglong2 za = *(const ulonglong2*)(z);       // batches b0..b0+3
        ulonglong2 zb = *(const ulonglong2*)(z + 4);   // batches b0+4..b0+7
        float4 w = *(const float4*)(Wc + kk * 16);     // 4 consecutive rows
        u64 w0 = pack2(w.x), w1 = pack2(w.y);
        u64 w2 = pack2(w.z), w3 = pack2(w.w);
        fma2(acc[0],  w0, za.x); fma2(acc[1],  w0, za.y);
        fma2(acc[2],  w0, zb.x); fma2(acc[3],  w0, zb.y);
        fma2(acc[4],  w1, za.x); fma2(acc[5],  w1, za.y);
        fma2(acc[6],  w1, zb.x); fma2(acc[7],  w1, zb.y);
        fma2(acc[8],  w2, za.x); fma2(acc[9],  w2, za.y);
        fma2(acc[10], w2, zb.x); fma2(acc[11], w2, zb.y);
        fma2(acc[12], w3, za.x); fma2(acc[13], w3, za.y);
        fma2(acc[14], w3, zb.x); fma2(acc[15], w3, zb.y);
    }
}

__global__ void __launch_bounds__(NT, 1) lstm_seq2seq_kernel(
    const float* __restrict__ sig, const int* __restrict__ tgt,
    const float* __restrict__ eWih, const float* __restrict__ eWhh,
    const float* __restrict__ eBih, const float* __restrict__ eBhh,
    const float* __restrict__ dWih, const float* __restrict__ dWhh,
    const float* __restrict__ dBih, const float* __restrict__ dBhh,
    const float* __restrict__ oW, const float* __restrict__ oB,
    float* __restrict__ out)
{
    extern __shared__ float sm[];
    float* Wsm     = sm;                               // [k][16]
    float* zB      = sm + W_FLOATS;                    // 5 buffers of 8192
    float* bias_sm = zB + NZB * Z_FLOATS;              // [16]
    float* lsc     = bias_sm + 16;                     // logits scratch (320)

#define ZBUF(i) (zB + (i) * Z_FLOATS)

    const int tid  = threadIdx.x;
    const int blk  = blockIdx.x;
    const int lane = tid & 31;
    const int ks   = tid >> 5;                   // k-split warp 0..7 (compute)
    const int rt   = lane & 3;                   // row group (= gate)
    const int bt   = lane >> 2;                  // batch group 0..7
    const int b0   = bt * 8;
    const int hb   = blk * HPB;
    const int b    = tid & 63;                   // cell-update batch
    const int hh_u = (tid >> 6) & 3;             // cell-update hidden 0..3
    const int gtid = blk * NT + tid;

    u64 gen  = *(volatile u64*)&g_barGen;        // step-gen base (monotonic)
    u64 igen = *(volatile u64*)&g_initGen;       // init-gen base

    // ---------------- init: tiled signal transpose [b][t][f] -> [t][f][b] ----------------
    {
        float* tileS = ZBUF(0);                  // 64x64 tile, pad 65
        for (int tile = blk; tile < S_LEN * 2; tile += NB) {
            int t = tile >> 1, f0 = (tile & 1) * 64;
            __syncthreads();
            for (int i = tid; i < 4096; i += NT) {
                int bb = i >> 6, ff = i & 63;
                tileS[ff * 65 + bb] = sig[((size_t)bb * S_LEN + t) * F_DIM + f0 + ff];
            }
            __syncthreads();
            for (int i = tid; i < 4096; i += NT) {
                int ff = i >> 6, bb = i & 63;
                g_sigT[(size_t)t * 8192 + (f0 + ff) * 64 + bb] = tileS[ff * 65 + bb];
            }
        }
    }
    for (int i = gtid; i < H_DIM * B_SZ; i += NB * NT) {
        g_hT[0][i] = 0.0f; g_hT[1][i] = 0.0f;
    }
    for (int i = gtid; i < H_DIM * V_DIM; i += NB * NT) {
        int v = i & 63, k2 = i >> 6;
        g_outWT[i] = oW[v * H_DIM + k2];
    }
    if (gtid < B_SZ) g_tok[gtid] = tgt[gtid * T_LEN];

    init_arrive(igen + 1);
    init_wait(igen + 1);

    // ---------------- warp 8: monitor (block 0) or retire ----------------
    if (tid >= NTC) {
        if (blk == 0) {
            int ml = tid - NTC;                  // 0..31, owns slots ml, ml+32, ml+64, ml+96
            u64 tg = gen;
            for (int i = 0; i < MON_GENS; ++i) {
                ++tg;
                bool ok;
                do {
                    ok = (ld_acq(&g_slot[ml * 16])        >= tg)
                      && (ld_acq(&g_slot[(ml + 32) * 16]) >= tg)
                      && (ld_acq(&g_slot[(ml + 64) * 16]) >= tg)
                      && (ld_acq(&g_slot[(ml + 96) * 16]) >= tg);
                } while (!__all_sync(0xffffffffu, ok));
                if (ml == 0) { __threadfence(); st_rel(&g_barGen, tg); }
            }
        }
        return;                                  // no block-wide syncs after this point
    }

    // ---------------- stage x(0) + encoder weights (256 threads) ----------------
    cp_chunk(ZBUF(0), g_sigT, tid);
    CP_COMMIT();
    for (int i = tid; i < 640 * 16; i += NTC) {
        int k2 = i >> 4, r = i & 15;
        int g = r >> 2, hhh = r & 3;
        int j = g * H_DIM + hb + hhh;
        Wsm[i] = (k2 < F_DIM) ? eWih[j * F_DIM + k2] : eWhh[j * H_DIM + (k2 - F_DIM)];
    }
    if (tid < 16) {
        int g = tid >> 2, hhh = tid & 3;
        int j = g * H_DIM + hb + hhh;
        bias_sm[tid] = eBih[j] + eBhh[j];
    }
    CP_WAIT(0);
    cbar();

    float c_reg = 0.0f;
    int cur = 0;
    u64 acc[16];

    // ---------------- encoder loop ----------------
    for (int t = 0; t < S_LEN; ++t) {
        float* zx = ZBUF(t & 1);
#pragma unroll
        for (int i = 0; i < 16; ++i) acc[i] = 0ULL;
        // x chunk: data prefetched last step; overlaps other blocks finishing
        compute_chunk(Wsm + (0 * 128 + ks * 16) * 16 + rt * 4, zx + ks * 1024 + b0, acc);
        // prefetch next x (read-only source; our own dead buffer)
        if (t + 1 < S_LEN) cp_chunk(ZBUF((t + 1) & 1), g_sigT + (size_t)(t + 1) * 8192, tid);
        CP_COMMIT();                                           // Cx
        step_wait(gen);                                        // h(t) visible
        const float* hsrc = g_hT[cur];
        cp_chunk(ZBUF(2), hsrc, tid);          CP_COMMIT();    // C1 = h0
        cp_chunk(ZBUF(3), hsrc + 8192, tid);   CP_COMMIT();    // C2 = h1
        cp_chunk(ZBUF(4), hsrc + 16384, tid);  CP_COMMIT();    // C3 = h2
        CP_WAIT(2); cbar();                                    // Cx,C1 done
        compute_chunk(Wsm + (1 * 128 + ks * 16) * 16 + rt * 4, ZBUF(2) + ks * 1024 + b0, acc);
        CP_WAIT(1); cbar();                                    // C2 done; ZBUF(2) free
        cp_chunk(ZBUF(2), hsrc + 24576, tid);  CP_COMMIT();    // C4 = h3 -> buf2
        compute_chunk(Wsm + (2 * 128 + ks * 16) * 16 + rt * 4, ZBUF(3) + ks * 1024 + b0, acc);
        CP_WAIT(1); cbar();                                    // C3 done
        compute_chunk(Wsm + (3 * 128 + ks * 16) * 16 + rt * 4, ZBUF(4) + ks * 1024 + b0, acc);
        CP_WAIT(0); cbar();                                    // C4 done
        compute_chunk(Wsm + (4 * 128 + ks * 16) * 16 + rt * 4, ZBUF(2) + ks * 1024 + b0, acc);

        // psum into dead x buffer
        float* psum = zx;
#pragma unroll
        for (int i = 0; i < 4; ++i) {
            ulonglong2* d = (ulonglong2*)(psum + ks * 1024 + (rt * 4 + i) * 64 + b0);
            d[0] = make_ulonglong2(acc[i * 4 + 0], acc[i * 4 + 1]);
            d[1] = make_ulonglong2(acc[i * 4 + 2], acc[i * 4 + 3]);
        }
        cbar();
        {
            float gv[4];
#pragma unroll
            for (int g = 0; g < 4; ++g) {
                float s = bias_sm[g * 4 + hh_u];
#pragma unroll
                for (int k2 = 0; k2 < 8; ++k2)
                    s += psum[k2 * 1024 + (g * 4 + hh_u) * 64 + b];
                gv[g] = s;
            }
            float cn = sigmoidf(gv[1]) * c_reg + sigmoidf(gv[0]) * tanhf(gv[2]);
            float hn = sigmoidf(gv[3]) * tanhf(cn);
            c_reg = cn;
            g_hT[cur ^ 1][(hb + hh_u) * 64 + b] = hn;
        }
        cur ^= 1;
        step_arrive(++gen, blk);
    }

    // ---------------- stage decoder weights ----------------
    step_wait(gen);                            // final h visible
    cbar();
    for (int i = tid; i < 16 * 512; i += NTC) {
        int k2 = i >> 4, r = i & 15;
        int g = r >> 2, hhh = r & 3;
        int j = g * H_DIM + hb + hhh;
        Wsm[(k2 + 128) * 16 + r] = dWhh[j * H_DIM + k2];   // k-major, offset past x part
    }
    if (tid < 16) {
        int g = tid >> 2, hhh = tid & 3;
        int j = g * H_DIM + hb + hhh;
        bias_sm[tid] = dBih[j] + dBhh[j];
    }
    cbar();

    // ---------------- decoder loop ----------------
    for (int s = 0; s < T_LEN; ++s) {
        const float* hsrc = g_hT[cur];
        cp_chunk(ZBUF(2), hsrc, tid);          CP_COMMIT();    // C1 = h0
        cp_chunk(ZBUF(3), hsrc + 8192, tid);   CP_COMMIT();    // C2 = h1
        cp_chunk(ZBUF(4), hsrc + 16384, tid);  CP_COMMIT();    // C3 = h2

#pragma unroll
        for (int i = 0; i < 16; ++i) acc[i] = 0ULL;

        // one-hot input gather (relu = identity on one-hot); overlaps cp latency
        float xg[4];
        {
            int tokb = g_tok[b];
#pragma unroll
            for (int g = 0; g < 4; ++g)
                xg[g] = __ldg(&dWih[((size_t)(g * H_DIM + hb + hh_u)) * V_DIM + tokb]);
        }

        CP_WAIT(2); cbar();                                    // C1 done
        compute_chunk(Wsm + (1 * 128 + ks * 16) * 16 + rt * 4, ZBUF(2) + ks * 1024 + b0, acc);
        CP_WAIT(1); cbar();                                    // C2 done; ZBUF(2) free
        cp_chunk(ZBUF(2), hsrc + 24576, tid);  CP_COMMIT();    // C4 = h3 -> buf2
        compute_chunk(Wsm + (2 * 128 + ks * 16) * 16 + rt * 4, ZBUF(3) + ks * 1024 + b0, acc);
        CP_WAIT(1); cbar();                                    // C3 done
        compute_chunk(Wsm + (3 * 128 + ks * 16) * 16 + rt * 4, ZBUF(4) + ks * 1024 + b0, acc);
        CP_WAIT(0); cbar();                                    // C4 done
        compute_chunk(Wsm + (4 * 128 + ks * 16) * 16 + rt * 4, ZBUF(2) + ks * 1024 + b0, acc);

        float* psum = ZBUF(0);
#pragma unroll
        for (int i = 0; i < 4; ++i) {
            ulonglong2* d = (ulonglong2*)(psum + ks * 1024 + (rt * 4 + i) * 64 + b0);
            d[0] = make_ulonglong2(acc[i * 4 + 0], acc[i * 4 + 1]);
            d[1] = make_ulonglong2(acc[i * 4 + 2], acc[i * 4 + 3]);
        }
        cbar();
        {
            float gv[4];
#pragma unroll
            for (int g = 0; g < 4; ++g) {
                float sv = bias_sm[g * 4 + hh_u] + xg[g];
#pragma unroll
                for (int k2 = 0; k2 < 8; ++k2)
                    sv += psum[k2 * 1024 + (g * 4 + hh_u) * 64 + b];
                gv[g] = sv;
            }
            float cn = sigmoidf(gv[1]) * c_reg + sigmoidf(gv[0]) * tanhf(gv[2]);
            float hn = sigmoidf(gv[3]) * tanhf(cn);
            c_reg = cn;
            g_hT[cur ^ 1][(hb + hh_u) * 64 + b] = hn;
        }
        cur ^= 1;
        step_arrive(++gen, blk);
        step_wait(gen);                        // new h visible everywhere

        // logits + argmax: block bb handles batch row bb
        if (blk < B_SZ) {
            int bb = blk;
            int v = tid & 63, part = tid >> 6;
            const float* hp = &g_hT[cur][part * 128 * 64 + bb];
            const float* wp = &g_outWT[part * 128 * 64 + v];
            float pr = 0.0f;
#pragma unroll 8
            for (int kk = 0; kk < 128; ++kk)
                pr += __ldg(&hp[kk * 64]) * __ldg(&wp[kk * 64]);
            lsc[part * 64 + v] = pr;
            cbar();
            if (part == 0) {
                float logit = oB[v] + lsc[v] + lsc[64 + v] + lsc[128 + v] + lsc[192 + v];
                lsc[256 + v] = logit;
                out[((size_t)bb * T_LEN + s) * V_DIM + v] = logit;
            }
            cbar();
            if (tid == 0) {
                float best = lsc[256];
                int bi = 0;
#pragma unroll 1
                for (int v2 = 1; v2 < 64; ++v2) {
                    float x = lsc[256 + v2];
                    if (x > best) { best = x; bi = v2; }
                }
                g_tok[bb] = bi;
            }
        }
        step_arrive(++gen, blk);
        step_wait(gen);                        // tok + logits visible
    }

    // ---------------- log_softmax (256 threads per block) ----------------
    {
        int wid = (blk * NTC + tid) >> 5;
        int ln  = tid & 31;
        for (int r = wid; r < B_SZ * T_LEN; r += (NB * NTC) / 32) {
            float* row = out + (size_t)r * V_DIM;
            float x0 = row[ln], x1 = row[ln + 32];
            float m = fmaxf(x0, x1);
#pragma unroll
            for (int o = 16; o > 0; o >>= 1)
                m = fmaxf(m, __shfl_xor_sync(0xffffffffu, m, o));
            float e = expf(x0 - m) + expf(x1 - m);
#pragma unroll
            for (int o = 16; o > 0; o >>= 1)
                e += __shfl_xor_sync(0xffffffffu, e, o);
            float lse = m + logf(e);
            row[ln] = x0 - lse;
            row[ln + 32] = x1 - lse;
        }
    }
}

extern "C" void kernel_launch(void* const* d_in, const int* in_sizes, int n_in,
                              void* d_out, int out_size) {
    (void)in_sizes; (void)n_in; (void)out_size;
    cudaFuncSetAttribute(lstm_seq2seq_kernel,
                         cudaFuncAttributeMaxDynamicSharedMemorySize, SMEM_BYTES);
    lstm_seq2seq_kernel<<<NB, NT, SMEM_BYTES>>>(
        (const float*)d_in[0],  (const int*)d_in[1],
        (const float*)d_in[2],  (const float*)d_in[3],
        (const float*)d_in[4],  (const float*)d_in[5],
        (const float*)d_in[6],  (const float*)d_in[7],
        (const float*)d_in[8],  (const float*)d_in[9],
        (const float*)d_in[10], (const float*)d_in[11],
        (float*)d_out);
}

// round 17
// speedup vs baseline: 1.4126x; 1.4126x over previous
#include <cuda_runtime.h>
#include <math.h>

#define NB 128
#define NT 256

typedef unsigned long long u64;

constexpr int S_LEN = 1024;
constexpr int B_SZ  = 64;
constexpr int F_DIM = 128;
constexpr int H_DIM = 512;
constexpr int V_DIM = 64;
constexpr int T_LEN = 64;
constexpr int HPB   = H_DIM / NB;        // 4 hidden units per block (16 gate rows)

constexpr int W_FLOATS = 640 * 16;       // Wsm[k][16 rows]
constexpr int Z_FLOATS = 128 * 64;       // one 32KB z chunk
constexpr int NZB      = 5;              // z buffers
constexpr int SMEM_FLOATS = W_FLOATS + NZB * Z_FLOATS + 16 + 384;
constexpr int SMEM_BYTES  = SMEM_FLOATS * 4;

// ---------------- persistent device state ----------------
__device__ float g_sigT[S_LEN * F_DIM * B_SZ];   // [t][f][b]
__device__ float g_hT[2][H_DIM * B_SZ];          // [k][b], double buffered
__device__ float g_outWT[H_DIM * V_DIM];         // [k][v]
__device__ int   g_tok[B_SZ];
__device__ u64 g_barCount;                       // monotonic across launches
__device__ u64 g_barGen;                         // monotonic across launches

// ---------------- barrier primitives (flat; fused-fence arrive) ----------------
__device__ __forceinline__ u64 ld_acq(const u64* p) {
    u64 v; asm volatile("ld.acquire.gpu.u64 %0, [%1];" : "=l"(v) : "l"(p) : "memory");
    return v;
}
__device__ __forceinline__ void st_rel(u64* p, u64 v) {
    asm volatile("st.release.gpu.u64 [%0], %1;" :: "l"(p), "l"(v) : "memory");
}
__device__ __forceinline__ void bar_arrive(u64 gen) {
    __syncthreads();
    if (threadIdx.x == 0) {
        u64 v;
        asm volatile("atom.acq_rel.gpu.global.add.u64 %0, [%1], 1;"
                     : "=l"(v) : "l"(&g_barCount) : "memory");
        if (v == gen * (u64)NB - 1ULL) {
            st_rel(&g_barGen, gen);              // release orders the atomic + all prior
        }
    }
}
__device__ __forceinline__ void bar_wait(u64 gen) {
    if (threadIdx.x == 0) {
        while (ld_acq(&g_barGen) < gen) { }
    }
    __syncthreads();
}

__device__ __forceinline__ float sigmoidf(float x) { return 1.0f / (1.0f + expf(-x)); }

// ---------------- packed f32x2 helpers ----------------
__device__ __forceinline__ u64 pack2(float x) {
    unsigned int u = __float_as_uint(x);
    u64 r; asm("mov.b64 %0, {%1, %1};" : "=l"(r) : "r"(u));
    return r;
}
__device__ __forceinline__ void fma2(u64& d, u64 a, u64 b) {
    asm("fma.rn.f32x2 %0, %1, %2, %0;" : "+l"(d) : "l"(a), "l"(b));
}

// ---------------- cp.async helpers ----------------
__device__ __forceinline__ void cp16(unsigned int dst, const float* src) {
    asm volatile("cp.async.ca.shared.global [%0], [%1], 16;" :: "r"(dst), "l"(src));
}
#define CP_COMMIT() asm volatile("cp.async.commit_group;" ::: "memory")
#define CP_WAIT(n)  asm volatile("cp.async.wait_group %0;" :: "n"(n) : "memory")

// stage a 128x64 chunk (8192 floats) smem <- gmem, 8 x 16B per thread
__device__ __forceinline__ void cp_chunk(float* dst, const float* src, int tid) {
    unsigned int d = (unsigned int)__cvta_generic_to_shared(dst) + tid * 16;
#pragma unroll
    for (int i = 0; i < 8; ++i)
        cp16(d + i * 4096, src + tid * 4 + i * 1024);
}

// ---------------- chunk compute: 16 k-values, 4 rows x 8 batches ----------------
__device__ __forceinline__ void compute_chunk(const float* __restrict__ Wc,
                                              const float* __restrict__ zc,
                                              u64 acc[16]) {
#pragma unroll
    for (int kk = 0; kk < 16; ++kk) {
        const float* z = zc + kk * 64;
        ulonglong2 za = *(const ulonglong2*)(z);       // batches b0..b0+3
        ulonglong2 zb = *(const ulonglong2*)(z + 4);   // batches b0+4..b0+7
        float4 w = *(const float4*)(Wc + kk * 16);     // 4 consecutive rows
        u64 w0 = pack2(w.x), w1 = pack2(w.y);
        u64 w2 = pack2(w.z), w3 = pack2(w.w);
        fma2(acc[0],  w0, za.x); fma2(acc[1],  w0, za.y);
        fma2(acc[2],  w0, zb.x); fma2(acc[3],  w0, zb.y);
        fma2(acc[4],  w1, za.x); fma2(acc[5],  w1, za.y);
        fma2(acc[6],  w1, zb.x); fma2(acc[7],  w1, zb.y);
        fma2(acc[8],  w2, za.x); fma2(acc[9],  w2, za.y);
        fma2(acc[10], w2, zb.x); fma2(acc[11], w2, zb.y);
        fma2(acc[12], w3, za.x); fma2(acc[13], w3, za.y);
        fma2(acc[14], w3, zb.x); fma2(acc[15], w3, zb.y);
    }
}

__global__ void __launch_bounds__(NT, 1) lstm_seq2seq_kernel(
    const float* __restrict__ sig, const int* __restrict__ tgt,
    const float* __restrict__ eWih, const float* __restrict__ eWhh,
    const float* __restrict__ eBih, const float* __restrict__ eBhh,
    const float* __restrict__ dWih, const float* __restrict__ dWhh,
    const float* __restrict__ dBih, const float* __restrict__ dBhh,
    const float* __restrict__ oW, const float* __restrict__ oB,
    float* __restrict__ out)
{
    extern __shared__ float sm[];
    float* Wsm     = sm;                               // [k][16]
    float* zB      = sm + W_FLOATS;                    // 5 buffers of 8192
    float* bias_sm = zB + NZB * Z_FLOATS;              // [16]
    float* lsc     = bias_sm + 16;                     // logits scratch (320)

#define ZBUF(i) (zB + (i) * Z_FLOATS)

    const int tid  = threadIdx.x;
    const int blk  = blockIdx.x;
    const int lane = tid & 31;
    const int ks   = tid >> 5;                   // k-split warp 0..7
    const int rt   = lane & 3;                   // row group (= gate)
    const int bt   = lane >> 2;                  // batch group 0..7
    const int b0   = bt * 8;
    const int hb   = blk * HPB;
    const int b    = tid & 63;                   // cell-update batch
    const int hh_u = tid >> 6;                   // cell-update hidden 0..3
    const int gtid = blk * NT + tid;

    u64 gen = *(volatile u64*)&g_barGen;

    // ---------------- init: tiled signal transpose [b][t][f] -> [t][f][b] ----------------
    {
        float* tileS = ZBUF(0);                  // 64x64 tile, pad 65
        for (int tile = blk; tile < S_LEN * 2; tile += NB) {
            int t = tile >> 1, f0 = (tile & 1) * 64;
            __syncthreads();
            for (int i = tid; i < 4096; i += NT) {
                int bb = i >> 6, ff = i & 63;
                tileS[ff * 65 + bb] = sig[((size_t)bb * S_LEN + t) * F_DIM + f0 + ff];
            }
            __syncthreads();
            for (int i = tid; i < 4096; i += NT) {
                int ff = i >> 6, bb = i & 63;
                g_sigT[(size_t)t * 8192 + (f0 + ff) * 64 + bb] = tileS[ff * 65 + bb];
            }
        }
    }
    for (int i = gtid; i < H_DIM * B_SZ; i += NB * NT) {
        g_hT[0][i] = 0.0f; g_hT[1][i] = 0.0f;
    }
    for (int i = gtid; i < H_DIM * V_DIM; i += NB * NT) {
        int v = i & 63, k2 = i >> 6;
        g_outWT[i] = oW[v * H_DIM + k2];
    }
    if (gtid < B_SZ) g_tok[gtid] = tgt[gtid * T_LEN];

    bar_arrive(++gen);
    bar_wait(gen);

    // ---------------- stage x(0) + encoder weights ----------------
    cp_chunk(ZBUF(0), g_sigT, tid);
    CP_COMMIT();
    for (int i = tid; i < 640 * 16; i += NT) {
        int k2 = i >> 4, r = i & 15;
        int g = r >> 2, hhh = r & 3;
        int j = g * H_DIM + hb + hhh;
        Wsm[i] = (k2 < F_DIM) ? eWih[j * F_DIM + k2] : eWhh[j * H_DIM + (k2 - F_DIM)];
    }
    if (tid < 16) {
        int g = tid >> 2, hhh = tid & 3;
        int j = g * H_DIM + hb + hhh;
        bias_sm[tid] = eBih[j] + eBhh[j];
    }
    CP_WAIT(0);
    __syncthreads();

    float c_reg = 0.0f;
    int cur = 0;
    u64 acc[16];

    // ---------------- encoder loop ----------------
    for (int t = 0; t < S_LEN; ++t) {
        float* zx = ZBUF(t & 1);
        // prefetch next x FIRST (earlier LSU issue, overlaps chunk0 + barrier)
        if (t + 1 < S_LEN) cp_chunk(ZBUF((t + 1) & 1), g_sigT + (size_t)(t + 1) * 8192, tid);
        CP_COMMIT();                                           // Cx
#pragma unroll
        for (int i = 0; i < 16; ++i) acc[i] = 0ULL;
        // x chunk: data prefetched last step; overlaps other blocks finishing
        compute_chunk(Wsm + (0 * 128 + ks * 16) * 16 + rt * 4, zx + ks * 1024 + b0, acc);
        bar_wait(gen);                                         // h(t) visible
        const float* hsrc = g_hT[cur];
        cp_chunk(ZBUF(2), hsrc, tid);          CP_COMMIT();    // C1 = h0
        cp_chunk(ZBUF(3), hsrc + 8192, tid);   CP_COMMIT();    // C2 = h1
        cp_chunk(ZBUF(4), hsrc + 16384, tid);  CP_COMMIT();    // C3 = h2
        CP_WAIT(2); __syncthreads();                           // Cx,C1 done
        compute_chunk(Wsm + (1 * 128 + ks * 16) * 16 + rt * 4, ZBUF(2) + ks * 1024 + b0, acc);
        CP_WAIT(1); __syncthreads();                           // C2 done; ZBUF(2) free
        cp_chunk(ZBUF(2), hsrc + 24576, tid);  CP_COMMIT();    // C4 = h3 -> buf2
        compute_chunk(Wsm + (2 * 128 + ks * 16) * 16 + rt * 4, ZBUF(3) + ks * 1024 + b0, acc);
        CP_WAIT(1); __syncthreads();                           // C3 done
        compute_chunk(Wsm + (3 * 128 + ks * 16) * 16 + rt * 4, ZBUF(4) + ks * 1024 + b0, acc);
        CP_WAIT(0); __syncthreads();                           // C4 done
        compute_chunk(Wsm + (4 * 128 + ks * 16) * 16 + rt * 4, ZBUF(2) + ks * 1024 + b0, acc);

        // psum into dead x buffer
        float* psum = zx;
#pragma unroll
        for (int i = 0; i < 4; ++i) {
            ulonglong2* d = (ulonglong2*)(psum + ks * 1024 + (rt * 4 + i) * 64 + b0);
            d[0] = make_ulonglong2(acc[i * 4 + 0], acc[i * 4 + 1]);
            d[1] = make_ulonglong2(acc[i * 4 + 2], acc[i * 4 + 3]);
        }
        __syncthreads();
        {
            float gv[4];
#pragma unroll
            for (int g = 0; g < 4; ++g) {
                float s = bias_sm[g * 4 + hh_u];
#pragma unroll
                for (int k2 = 0; k2 < 8; ++k2)
                    s += psum[k2 * 1024 + (g * 4 + hh_u) * 64 + b];
                gv[g] = s;
            }
            float cn = sigmoidf(gv[1]) * c_reg + sigmoidf(gv[0]) * tanhf(gv[2]);
            float hn = sigmoidf(gv[3]) * tanhf(cn);
            c_reg = cn;
            g_hT[cur ^ 1][(hb + hh_u) * 64 + b] = hn;
        }
        cur ^= 1;
        bar_arrive(++gen);
    }

    // ---------------- stage decoder weights ----------------
    bar_wait(gen);                             // final h visible; tok(0) ready since init
    __syncthreads();
    for (int i = tid; i < 16 * 512; i += NT) {
        int k2 = i >> 4, r = i & 15;
        int g = r >> 2, hhh = r & 3;
        int j = g * H_DIM + hb + hhh;
        Wsm[(k2 + 128) * 16 + r] = dWhh[j * H_DIM + k2];   // k-major, offset past x part
    }
    if (tid < 16) {
        int g = tid >> 2, hhh = tid & 3;
        int j = g * H_DIM + hb + hhh;
        bias_sm[tid] = dBih[j] + dBhh[j];
    }
    __syncthreads();

    // ---------------- decoder loop (re-pipelined: tok-wait AFTER chunk compute) --
    for (int s = 0; s < T_LEN; ++s) {
        // h(s) is valid here (guarded by the h-barrier of the previous iteration)
        const float* hsrc = g_hT[cur];
        cp_chunk(ZBUF(2), hsrc, tid);          CP_COMMIT();    // C1 = h0
        cp_chunk(ZBUF(3), hsrc + 8192, tid);   CP_COMMIT();    // C2 = h1
        cp_chunk(ZBUF(4), hsrc + 16384, tid);  CP_COMMIT();    // C3 = h2

#pragma unroll
        for (int i = 0; i < 16; ++i) acc[i] = 0ULL;

        CP_WAIT(2); __syncthreads();                           // C1 done
        compute_chunk(Wsm + (1 * 128 + ks * 16) * 16 + rt * 4, ZBUF(2) + ks * 1024 + b0, acc);
        CP_WAIT(1); __syncthreads();                           // C2 done; ZBUF(2) free
        cp_chunk(ZBUF(2), hsrc + 24576, tid);  CP_COMMIT();    // C4 = h3 -> buf2
        compute_chunk(Wsm + (2 * 128 + ks * 16) * 16 + rt * 4, ZBUF(3) + ks * 1024 + b0, acc);
        CP_WAIT(1); __syncthreads();                           // C3 done
        compute_chunk(Wsm + (3 * 128 + ks * 16) * 16 + rt * 4, ZBUF(4) + ks * 1024 + b0, acc);
        CP_WAIT(0); __syncthreads();                           // C4 done
        compute_chunk(Wsm + (4 * 128 + ks * 16) * 16 + rt * 4, ZBUF(2) + ks * 1024 + b0, acc);

        // tok(s) barrier: released by last iteration's logits blocks — overlapped
        // with the chunk compute above. (s=0: already satisfied by encoder-exit wait.)
        if (s > 0) bar_wait(gen);

        // one-hot input gather (relu = identity on one-hot)
        float xg[4];
        {
            int tokb = g_tok[b];
#pragma unroll
            for (int g = 0; g < 4; ++g)
                xg[g] = __ldg(&dWih[((size_t)(g * H_DIM + hb + hh_u)) * V_DIM + tokb]);
        }

        float* psum = ZBUF(0);
#pragma unroll
        for (int i = 0; i < 4; ++i) {
            ulonglong2* d = (ulonglong2*)(psum + ks * 1024 + (rt * 4 + i) * 64 + b0);
            d[0] = make_ulonglong2(acc[i * 4 + 0], acc[i * 4 + 1]);
            d[1] = make_ulonglong2(acc[i * 4 + 2], acc[i * 4 + 3]);
        }
        __syncthreads();
        {
            float gv[4];
#pragma unroll
            for (int g = 0; g < 4; ++g) {
                float sv = bias_sm[g * 4 + hh_u] + xg[g];
#pragma unroll
                for (int k2 = 0; k2 < 8; ++k2)
                    sv += psum[k2 * 1024 + (g * 4 + hh_u) * 64 + b];
                gv[g] = sv;
            }
            float cn = sigmoidf(gv[1]) * c_reg + sigmoidf(gv[0]) * tanhf(gv[2]);
            float hn = sigmoidf(gv[3]) * tanhf(cn);
            c_reg = cn;
            g_hT[cur ^ 1][(hb + hh_u) * 64 + b] = hn;
        }
        cur ^= 1;
        bar_arrive(++gen);
        bar_wait(gen);                         // h(s+1) visible everywhere

        // logits + argmax: block bb handles batch row bb
        if (blk < B_SZ) {
            int bb = blk;
            int v = tid & 63, part = tid >> 6;
            const float* hp = &g_hT[cur][part * 128 * 64 + bb];
            const float* wp = &g_outWT[part * 128 * 64 + v];
            float pr = 0.0f;
#pragma unroll 8
            for (int kk = 0; kk < 128; ++kk)
                pr += __ldg(&hp[kk * 64]) * __ldg(&wp[kk * 64]);
            lsc[part * 64 + v] = pr;
            __syncthreads();
            if (part == 0) {
                float logit = oB[v] + lsc[v] + lsc[64 + v] + lsc[128 + v] + lsc[192 + v];
                lsc[256 + v] = logit;
                out[((size_t)bb * T_LEN + s) * V_DIM + v] = logit;
            }
            __syncthreads();
            if (tid == 0) {
                float best = lsc[256];
                int bi = 0;
#pragma unroll 1
                for (int v2 = 1; v2 < 64; ++v2) {
                    float x = lsc[256 + v2];
                    if (x > best) { best = x; bi = v2; }
                }
                g_tok[bb] = bi;
            }
        }
        bar_arrive(++gen);                     // tok(s+1) ready — NO wait here
    }
    bar_wait(gen);                             // all logits + toks visible for softmax

    // ---------------- log_softmax (in place on out) ----------------
    {
        int wid = gtid >> 5;
        int ln  = tid & 31;
        for (int r = wid; r < B_SZ * T_LEN; r += (NB * NT) / 32) {
            float* row = out + (size_t)r * V_DIM;
            float x0 = row[ln], x1 = row[ln + 32];
            float m = fmaxf(x0, x1);
#pragma unroll
            for (int o = 16; o > 0; o >>= 1)
                m = fmaxf(m, __shfl_xor_sync(0xffffffffu, m, o));
            float e = expf(x0 - m) + expf(x1 - m);
#pragma unroll
            for (int o = 16; o > 0; o >>= 1)
                e += __shfl_xor_sync(0xffffffffu, e, o);
            float lse = m + logf(e);
            row[ln] = x0 - lse;
            row[ln + 32] = x1 - lse;
        }
    }
}

extern "C" void kernel_launch(void* const* d_in, const int* in_sizes, int n_in,
                              void* d_out, int out_size) {
    (void)in_sizes; (void)n_in; (void)out_size;
    cudaFuncSetAttribute(lstm_seq2seq_kernel,
                         cudaFuncAttributeMaxDynamicSharedMemorySize, SMEM_BYTES);
    lstm_seq2seq_kernel<<<NB, NT, SMEM_BYTES>>>(
        (const float*)d_in[0],  (const int*)d_in[1],
        (const float*)d_in[2],  (const float*)d_in[3],
        (const float*)d_in[4],  (const float*)d_in[5],
        (const float*)d_in[6],  (const float*)d_in[7],
        (const float*)d_in[8],  (const float*)d_in[9],
        (const float*)d_in[10], (const float*)d_in[11],
        (float*)d_out);
}